// round 2
// baseline (speedup 1.0000x reference)
#include <cuda_runtime.h>
#include <cstdint>

// NearestEmbed: x (64,64,32,32) f32, emb (64,512) f32
// out (all float32) = [ quantized (64,64,32,32) | argmin (64,32,32) as float ]
//
// Per spatial row n (D=64 channels, stride 1024 floats in x):
//   k* = argmin_k ( ||e_k||^2 - 2 * x . e_k )   ascending k, strict <  => first min (jnp.argmin)
//
// Codebook transposed into smem (embT[k][d], stride 68 floats), x row in 32
// f32x2 register pairs, dot product via packed fma.rn.f32x2 with 8 chains.

#define EMB_D 64
#define EMB_K 512
#define ROW_STRIDE 68
#define THREADS 512
#define HW 1024
#define N_ROWS 65536
#define X_BATCH_STRIDE 65536

__device__ __forceinline__ void ffma2(unsigned long long& d, unsigned long long a, unsigned long long b) {
    asm("fma.rn.f32x2 %0, %1, %2, %0;" : "+l"(d) : "l"(a), "l"(b));
}
__device__ __forceinline__ void fmul2(unsigned long long& d, unsigned long long a, unsigned long long b) {
    asm("mul.rn.f32x2 %0, %1, %2;" : "=l"(d) : "l"(a), "l"(b));
}
__device__ __forceinline__ void fadd2(unsigned long long& d, unsigned long long a) {
    asm("add.rn.f32x2 %0, %0, %1;" : "+l"(d) : "l"(a));
}
__device__ __forceinline__ unsigned long long pack2(float lo, float hi) {
    unsigned long long r;
    asm("mov.b64 %0, {%1, %2};" : "=l"(r) : "f"(lo), "f"(hi));
    return r;
}
__device__ __forceinline__ void unpack2(float& lo, float& hi, unsigned long long v) {
    asm("mov.b64 {%0, %1}, %2;" : "=f"(lo), "=f"(hi) : "l"(v));
}

__global__ __launch_bounds__(THREADS, 1)
void vq_argmin_kernel(const float* __restrict__ x,
                      const float* __restrict__ emb,
                      float* __restrict__ out_q,
                      float* __restrict__ out_idx)
{
    extern __shared__ float smem[];
    float* embT  = smem;                        // [EMB_K][ROW_STRIDE]
    float* norms = smem + EMB_K * ROW_STRIDE;   // [EMB_K]

    const int tid = threadIdx.x;

    // Transpose-load codebook: emb is d-major [64][512] -> embT[k][d]
    #pragma unroll
    for (int idx = tid; idx < EMB_D * EMB_K; idx += THREADS) {
        int d = idx >> 9;
        int k = idx & (EMB_K - 1);
        embT[k * ROW_STRIDE + d] = emb[idx];
    }
    __syncthreads();

    // ||e_k||^2
    if (tid < EMB_K) {
        const float* r = embT + tid * ROW_STRIDE;
        float s = 0.f;
        #pragma unroll
        for (int d = 0; d < EMB_D; d++) s = fmaf(r[d], r[d], s);
        norms[tid] = s;
    }
    __syncthreads();

    const int n  = blockIdx.x * THREADS + tid;
    const int b  = n >> 10;
    const int hw = n & (HW - 1);
    const float* xr = x + (size_t)b * X_BATCH_STRIDE + hw;

    unsigned long long xp[32];
    #pragma unroll
    for (int i = 0; i < 32; i++) {
        float a0 = __ldg(xr + (size_t)(2 * i) * HW);
        float a1 = __ldg(xr + (size_t)(2 * i + 1) * HW);
        xp[i] = pack2(a0, a1);
    }

    float best = __int_as_float(0x7f800000);     // +inf
    int bidx = 0;

    for (int k = 0; k < EMB_K; k++) {
        const ulonglong2* row = reinterpret_cast<const ulonglong2*>(embT + k * ROW_STRIDE);
        unsigned long long accA[4], accB[4];
        #pragma unroll
        for (int j = 0; j < 16; j++) {
            ulonglong2 v = row[j];               // LDS.128 broadcast
            if (j < 4) {
                fmul2(accA[j], xp[2 * j],     v.x);
                fmul2(accB[j], xp[2 * j + 1], v.y);
            } else {
                ffma2(accA[j & 3], xp[2 * j],     v.x);
                ffma2(accB[j & 3], xp[2 * j + 1], v.y);
            }
        }
        fadd2(accA[0], accA[1]);
        fadd2(accA[2], accA[3]);
        fadd2(accB[0], accB[1]);
        fadd2(accB[2], accB[3]);
        fadd2(accA[0], accA[2]);
        fadd2(accB[0], accB[2]);
        fadd2(accA[0], accB[0]);
        float lo, hi;
        unpack2(lo, hi, accA[0]);
        float dot = lo + hi;
        float score = fmaf(-2.f, dot, norms[k]);
        if (score < best) { best = score; bidx = k; }
    }

    out_idx[n] = (float)bidx;   // output buffer dtype is float32

    const float* brow = embT + bidx * ROW_STRIDE;
    float* o = out_q + (size_t)b * X_BATCH_STRIDE + hw;
    #pragma unroll
    for (int d = 0; d < EMB_D; d++) {
        o[(size_t)d * HW] = brow[d];
    }
}

extern "C" void kernel_launch(void* const* d_in, const int* in_sizes, int n_in,
                              void* d_out, int out_size)
{
    const float* x   = (const float*)d_in[0];   // 4194304 f32
    const float* emb = (const float*)d_in[1];   // 32768 f32
    float* out_q = (float*)d_out;
    float* out_i = (float*)d_out + (size_t)64 * EMB_D * HW;  // after 4194304 floats

    size_t smem_bytes = (size_t)(EMB_K * ROW_STRIDE + EMB_K) * sizeof(float);
    cudaFuncSetAttribute(vq_argmin_kernel,
                         cudaFuncAttributeMaxDynamicSharedMemorySize, (int)smem_bytes);

    vq_argmin_kernel<<<N_ROWS / THREADS, THREADS, smem_bytes>>>(x, emb, out_q, out_i);
}

// round 3
// speedup vs baseline: 1.1623x; 1.1623x over previous
#include <cuda_runtime.h>
#include <cstdint>

// NearestEmbed: x (64,64,32,32) f32, emb (64,512) f32
// out (all float32) = [ quantized (64,64,32,32) | argmin (64,32,32) as float ]
//
// R3: register-block Mr=2 rows per thread so each codebook LDS.128 feeds 4 FFMA2
// (was 2). 256 thr/block, 128 blocks, 1 CTA/SM (139KB smem codebook).
// x is pre-scaled by -2 at load (exact power-of-2), so score = acc + ||e_k||^2.

#define EMB_D 64
#define EMB_K 512
#define ROW_STRIDE 68           // floats per embT row (272B = 17*16B, 16B aligned)
#define THREADS 256
#define MR 2
#define ROWS_PER_BLOCK (THREADS * MR)   // 512
#define HW 1024                 // H*W
#define N_ROWS 65536            // B*H*W
#define X_BATCH_STRIDE 65536    // D*H*W floats

__device__ __forceinline__ void ffma2(unsigned long long& d, unsigned long long a, unsigned long long b) {
    asm("fma.rn.f32x2 %0, %1, %2, %0;" : "+l"(d) : "l"(a), "l"(b));
}
__device__ __forceinline__ void fmul2(unsigned long long& d, unsigned long long a, unsigned long long b) {
    asm("mul.rn.f32x2 %0, %1, %2;" : "=l"(d) : "l"(a), "l"(b));
}
__device__ __forceinline__ void fadd2(unsigned long long& d, unsigned long long a) {
    asm("add.rn.f32x2 %0, %0, %1;" : "+l"(d) : "l"(a));
}
__device__ __forceinline__ unsigned long long pack2(float lo, float hi) {
    unsigned long long r;
    asm("mov.b64 %0, {%1, %2};" : "=l"(r) : "f"(lo), "f"(hi));
    return r;
}
__device__ __forceinline__ void unpack2(float& lo, float& hi, unsigned long long v) {
    asm("mov.b64 {%0, %1}, %2;" : "=f"(lo), "=f"(hi) : "l"(v));
}

__global__ __launch_bounds__(THREADS, 1)
void vq_argmin_kernel(const float* __restrict__ x,
                      const float* __restrict__ emb,
                      float* __restrict__ out_q,
                      float* __restrict__ out_idx)
{
    extern __shared__ float smem[];
    float* embT  = smem;                        // [EMB_K][ROW_STRIDE]
    float* norms = smem + EMB_K * ROW_STRIDE;   // [EMB_K]

    const int tid = threadIdx.x;

    // Transpose-load codebook: emb is d-major [64][512] -> embT[k][d]
    for (int idx = tid; idx < EMB_D * EMB_K; idx += THREADS) {
        int d = idx >> 9;
        int k = idx & (EMB_K - 1);
        embT[k * ROW_STRIDE + d] = emb[idx];
    }
    __syncthreads();

    // ||e_k||^2 (each thread does 2 codes)
    #pragma unroll
    for (int kk = 0; kk < 2; kk++) {
        int k = tid + kk * THREADS;
        const float* r = embT + k * ROW_STRIDE;
        float s = 0.f;
        #pragma unroll
        for (int d = 0; d < EMB_D; d++) s = fmaf(r[d], r[d], s);
        norms[k] = s;
    }
    __syncthreads();

    // Two rows per thread: n0 and n0 + THREADS (same batch b within a block)
    const int n0 = blockIdx.x * ROWS_PER_BLOCK + tid;
    const int n1 = n0 + THREADS;
    const int b  = n0 >> 10;
    const int hw0 = n0 & (HW - 1);
    const int hw1 = n1 & (HW - 1);
    const float* xr0 = x + (size_t)b * X_BATCH_STRIDE + hw0;
    const float* xr1 = x + (size_t)b * X_BATCH_STRIDE + hw1;

    // Load x rows pre-scaled by -2 (exact), packed as f32x2 over d-pairs.
    unsigned long long xp0[32], xp1[32];
    #pragma unroll
    for (int i = 0; i < 32; i++) {
        float a0 = -2.0f * __ldg(xr0 + (size_t)(2 * i) * HW);
        float a1 = -2.0f * __ldg(xr0 + (size_t)(2 * i + 1) * HW);
        xp0[i] = pack2(a0, a1);
        float c0 = -2.0f * __ldg(xr1 + (size_t)(2 * i) * HW);
        float c1 = -2.0f * __ldg(xr1 + (size_t)(2 * i + 1) * HW);
        xp1[i] = pack2(c0, c1);
    }

    float best0 = __int_as_float(0x7f800000);
    float best1 = __int_as_float(0x7f800000);
    int bidx0 = 0, bidx1 = 0;

    for (int k = 0; k < EMB_K; k++) {
        const ulonglong2* row = reinterpret_cast<const ulonglong2*>(embT + k * ROW_STRIDE);
        unsigned long long a0[4], a1[4];
        #pragma unroll
        for (int j = 0; j < 16; j++) {
            ulonglong2 v = row[j];               // LDS.128 broadcast, shared by both rows
            int cx = (2 * j) & 3;
            int cy = (2 * j + 1) & 3;
            if (j < 2) {
                fmul2(a0[cx], xp0[2 * j],     v.x);
                fmul2(a0[cy], xp0[2 * j + 1], v.y);
                fmul2(a1[cx], xp1[2 * j],     v.x);
                fmul2(a1[cy], xp1[2 * j + 1], v.y);
            } else {
                ffma2(a0[cx], xp0[2 * j],     v.x);
                ffma2(a0[cy], xp0[2 * j + 1], v.y);
                ffma2(a1[cx], xp1[2 * j],     v.x);
                ffma2(a1[cy], xp1[2 * j + 1], v.y);
            }
        }
        float nk = norms[k];

        fadd2(a0[0], a0[1]); fadd2(a0[2], a0[3]); fadd2(a0[0], a0[2]);
        float lo0, hi0; unpack2(lo0, hi0, a0[0]);
        float s0 = (lo0 + hi0) + nk;
        if (s0 < best0) { best0 = s0; bidx0 = k; }

        fadd2(a1[0], a1[1]); fadd2(a1[2], a1[3]); fadd2(a1[0], a1[2]);
        float lo1, hi1; unpack2(lo1, hi1, a1[0]);
        float s1 = (lo1 + hi1) + nk;
        if (s1 < best1) { best1 = s1; bidx1 = k; }
    }

    out_idx[n0] = (float)bidx0;
    out_idx[n1] = (float)bidx1;

    // Gather winning codes (coalesced across warp per d)
    const float* br0 = embT + bidx0 * ROW_STRIDE;
    const float* br1 = embT + bidx1 * ROW_STRIDE;
    float* o0 = out_q + (size_t)b * X_BATCH_STRIDE + hw0;
    float* o1 = out_q + (size_t)b * X_BATCH_STRIDE + hw1;
    #pragma unroll
    for (int d = 0; d < EMB_D; d++) {
        o0[(size_t)d * HW] = br0[d];
        o1[(size_t)d * HW] = br1[d];
    }
}

extern "C" void kernel_launch(void* const* d_in, const int* in_sizes, int n_in,
                              void* d_out, int out_size)
{
    const float* x   = (const float*)d_in[0];   // 4194304 f32
    const float* emb = (const float*)d_in[1];   // 32768 f32
    float* out_q = (float*)d_out;
    float* out_i = (float*)d_out + (size_t)64 * EMB_D * HW;  // after 4194304 floats

    size_t smem_bytes = (size_t)(EMB_K * ROW_STRIDE + EMB_K) * sizeof(float);
    cudaFuncSetAttribute(vq_argmin_kernel,
                         cudaFuncAttributeMaxDynamicSharedMemorySize, (int)smem_bytes);

    vq_argmin_kernel<<<N_ROWS / ROWS_PER_BLOCK, THREADS, smem_bytes>>>(x, emb, out_q, out_i);
}

// round 6
// speedup vs baseline: 2.6552x; 2.2844x over previous
#include <cuda_runtime.h>
#include <cuda_fp16.h>
#include <cstdint>

// NearestEmbed: x (64,64,32,32) f32, emb (64,512) f32
// out f32 = [ quantized 4194304 | argmin 65536 (as float) ]
//
// R6: HMMA (mma.sync.m16n8k16 f16, baseline PTX -> compiles for plain sm_103)
// coarse scores + top-2 margin test; rare rows get an exact fp32 warp-coop
// rescan from the smem fp32 codebook. Coarse winner == exact winner whenever
// coarse gap > MARGIN >= 2*coarse error.

#define THREADS 512            // 16 warps, warp handles 16 rows
#define TILE_M 256             // rows per CTA tile
#define GRID 128
#define TILES_PER_CTA 2        // 256 tiles total / 128 CTAs
#define EMB_D 64
#define EMB_K 512
#define HW 1024
#define MARGIN 0.04f

// smem layout (bytes)
#define SM_FRAGS 0                       // u32 frags[64 ntile][4 kstep][32 lane][2] = 64KB
#define SM_EMB   65536                   // f32 emb_s[64][512] = 128KB
#define SM_NORMS (SM_EMB + 131072)       // f32 [512] = 2KB
#define SM_WIN   (SM_NORMS + 2048)       // i32 [256]
#define SM_QUEUE (SM_WIN + 1024)         // i32 [256]
#define SM_QCNT  (SM_QUEUE + 1024)       // i32
#define SM_XS    (SM_QCNT + 16)          // f32 [16 warps][64] = 4KB scratch
#define SM_TOTAL (SM_XS + 4096)

__device__ __forceinline__ uint32_t packh2(float a, float b) {
    __half2 h = __floats2half2_rn(a, b);
    return *reinterpret_cast<uint32_t*>(&h);
}

__device__ __forceinline__ void hmma16816(float& c0, float& c1, float& c2, float& c3,
                                          uint32_t a0, uint32_t a1, uint32_t a2, uint32_t a3,
                                          uint32_t b0, uint32_t b1) {
    asm volatile("mma.sync.aligned.m16n8k16.row.col.f32.f16.f16.f32 "
                 "{%0,%1,%2,%3}, {%4,%5,%6,%7}, {%8,%9}, {%0,%1,%2,%3};"
                 : "+f"(c0), "+f"(c1), "+f"(c2), "+f"(c3)
                 : "r"(a0), "r"(a1), "r"(a2), "r"(a3), "r"(b0), "r"(b1));
}

__global__ __launch_bounds__(THREADS, 1)
void vq_hmma_kernel(const float* __restrict__ x,
                    const float* __restrict__ emb,
                    float* __restrict__ out_q,
                    float* __restrict__ out_idx)
{
    extern __shared__ char smem[];
    uint32_t* frags = reinterpret_cast<uint32_t*>(smem + SM_FRAGS);
    float*    emb_s = reinterpret_cast<float*>(smem + SM_EMB);
    float*    norms = reinterpret_cast<float*>(smem + SM_NORMS);
    int*      winners = reinterpret_cast<int*>(smem + SM_WIN);
    int*      queue   = reinterpret_cast<int*>(smem + SM_QUEUE);
    int*      qcnt    = reinterpret_cast<int*>(smem + SM_QCNT);
    float*    xscr    = reinterpret_cast<float*>(smem + SM_XS);

    const int tid  = threadIdx.x;
    const int warp = tid >> 5;
    const int lane = tid & 31;
    const int gidq = lane & 3;        // threadID in group
    const int grp  = lane >> 2;       // groupID (0..7)

    // ---- Prologue (once per CTA) ----
    for (int i = tid; i < EMB_D * EMB_K; i += THREADS) emb_s[i] = emb[i];
    if (tid == 0) *qcnt = 0;
    __syncthreads();

    for (int k = tid; k < EMB_K; k += THREADS) {
        float s = 0.f;
        #pragma unroll
        for (int d = 0; d < EMB_D; d++) {
            float v = emb_s[d * EMB_K + k];
            s = fmaf(v, v, s);
        }
        norms[k] = s;
    }
    // B fragments: frags[((nt*4+ks)*32 + lane)*2 + j]
    //   n = nt*8 + lane/4 ; d0 = ks*16 + 2*(lane%4) + 8*j ; value = half2(e[d0][n], e[d0+1][n])
    for (int f = tid; f < 64 * 4 * 32 * 2; f += THREADS) {
        int j  = f & 1;
        int ln = (f >> 1) & 31;
        int ks = (f >> 6) & 3;
        int nt = f >> 8;
        int n  = nt * 8 + (ln >> 2);
        int d0 = ks * 16 + 2 * (ln & 3) + 8 * j;
        frags[f] = packh2(emb_s[d0 * EMB_K + n], emb_s[(d0 + 1) * EMB_K + n]);
    }
    __syncthreads();

    for (int it = 0; it < TILES_PER_CTA; it++) {
        const int tile = blockIdx.x * TILES_PER_CTA + it;
        const int row_base = tile * TILE_M;
        const int b = row_base >> 10;
        const int hw_base = row_base & (HW - 1);
        const float* xb = x + (size_t)b * (EMB_D * HW) + hw_base;   // x(row, d) = xb[d*HW + row]

        // ---- A fragments: this warp's 16 rows [warp*16, warp*16+16) ----
        const float* xw = xb + warp * 16;
        uint32_t A[4][4];
        {
            const int q2 = gidq * 2;
            #pragma unroll
            for (int ks = 0; ks < 4; ks++) {
                int d = ks * 16 + q2;
                A[ks][0] = packh2(xw[d * HW + grp],           xw[(d + 1) * HW + grp]);
                A[ks][1] = packh2(xw[d * HW + grp + 8],       xw[(d + 1) * HW + grp + 8]);
                A[ks][2] = packh2(xw[(d + 8) * HW + grp],     xw[(d + 9) * HW + grp]);
                A[ks][3] = packh2(xw[(d + 8) * HW + grp + 8], xw[(d + 9) * HW + grp + 8]);
            }
        }

        // ---- coarse scan over 64 n-tiles ----
        float b1a = __int_as_float(0x7f800000), b2a = b1a; int k1a = 0;  // row grp
        float b1b = b1a, b2b = b1a; int k1b = 0;                          // row grp+8

        const uint2* fr2 = reinterpret_cast<const uint2*>(frags);
        #pragma unroll 4
        for (int nt = 0; nt < 64; nt++) {
            float c0 = 0.f, c1 = 0.f, c2 = 0.f, c3 = 0.f;
            #pragma unroll
            for (int ks = 0; ks < 4; ks++) {
                uint2 bb = fr2[(nt * 4 + ks) * 32 + lane];
                hmma16816(c0, c1, c2, c3, A[ks][0], A[ks][1], A[ks][2], A[ks][3], bb.x, bb.y);
            }
            const int n0 = nt * 8 + gidq * 2;
            float2 nr = *reinterpret_cast<const float2*>(norms + n0);
            float s0 = fmaf(-2.f, c0, nr.x);
            float s1 = fmaf(-2.f, c1, nr.y);
            float s2 = fmaf(-2.f, c2, nr.x);
            float s3 = fmaf(-2.f, c3, nr.y);
            // row a (grp): s0 (k=n0), s1 (k=n0+1)
            if (s0 < b1a) { b2a = b1a; b1a = s0; k1a = n0; } else b2a = fminf(b2a, s0);
            if (s1 < b1a) { b2a = b1a; b1a = s1; k1a = n0 + 1; } else b2a = fminf(b2a, s1);
            // row b (grp+8): s2, s3
            if (s2 < b1b) { b2b = b1b; b1b = s2; k1b = n0; } else b2b = fminf(b2b, s2);
            if (s3 < b1b) { b2b = b1b; b1b = s3; k1b = n0 + 1; } else b2b = fminf(b2b, s3);
        }

        // ---- merge across the 4 lanes of each row-group (xor 1, xor 2) ----
        #pragma unroll
        for (int off = 1; off <= 2; off <<= 1) {
            float ob1 = __shfl_xor_sync(0xffffffffu, b1a, off);
            int   ok1 = __shfl_xor_sync(0xffffffffu, k1a, off);
            float ob2 = __shfl_xor_sync(0xffffffffu, b2a, off);
            float nb2 = fminf(fmaxf(b1a, ob1), fminf(b2a, ob2));
            bool take = (ob1 < b1a) || (ob1 == b1a && ok1 < k1a);
            b1a = take ? ob1 : b1a; k1a = take ? ok1 : k1a; b2a = nb2;

            float pb1 = __shfl_xor_sync(0xffffffffu, b1b, off);
            int   pk1 = __shfl_xor_sync(0xffffffffu, k1b, off);
            float pb2 = __shfl_xor_sync(0xffffffffu, b2b, off);
            float qb2 = fminf(fmaxf(b1b, pb1), fminf(b2b, pb2));
            bool tk2 = (pb1 < b1b) || (pb1 == b1b && pk1 < k1b);
            b1b = tk2 ? pb1 : b1b; k1b = tk2 ? pk1 : k1b; b2b = qb2;
        }

        if (gidq == 0) {
            int lr = warp * 16 + grp;
            if (b2a - b1a <= MARGIN) { int qi = atomicAdd(qcnt, 1); queue[qi] = lr; }
            else winners[lr] = k1a;
            int lr2 = lr + 8;
            if (b2b - b1b <= MARGIN) { int qi = atomicAdd(qcnt, 1); queue[qi] = lr2; }
            else winners[lr2] = k1b;
        }
        __syncthreads();

        // ---- exact fp32 rescan for ambiguous rows (rare) ----
        const int nq = *qcnt;
        for (int i = warp; i < nq; i += 16) {
            int lr = queue[i];
            const float* xg = xb + lr;                 // xg[d*HW]
            float* xs = xscr + warp * 64;
            xs[lane] = xg[(size_t)lane * HW];
            xs[lane + 32] = xg[(size_t)(lane + 32) * HW];
            __syncwarp();
            float best = __int_as_float(0x7f800000);
            int bk = 0;
            #pragma unroll
            for (int j = 0; j < 16; j++) {
                int k = lane + 32 * j;
                float acc = 0.f;
                #pragma unroll
                for (int d = 0; d < EMB_D; d++)
                    acc = fmaf(xs[d], emb_s[d * EMB_K + k], acc);
                float sc = fmaf(-2.f, acc, norms[k]);
                if (sc < best) { best = sc; bk = k; }   // within lane k ascending
            }
            #pragma unroll
            for (int off = 16; off >= 1; off >>= 1) {
                float os = __shfl_xor_sync(0xffffffffu, best, off);
                int   ok = __shfl_xor_sync(0xffffffffu, bk, off);
                bool take = (os < best) || (os == best && ok < bk);
                best = take ? os : best;
                bk = take ? ok : bk;
            }
            if (lane == 0) winners[lr] = bk;
            __syncwarp();
        }
        __syncthreads();

        // ---- outputs ----
        float* oq = out_q + (size_t)b * (EMB_D * HW) + hw_base;
        for (int i = tid; i < TILE_M * EMB_D; i += THREADS) {
            int r = i & (TILE_M - 1);
            int d = i >> 8;                    // TILE_M = 256
            oq[(size_t)d * HW + r] = emb_s[d * EMB_K + winners[r]];
        }
        if (tid < TILE_M) out_idx[row_base + tid] = (float)winners[tid];
        if (tid == 0) *qcnt = 0;
        __syncthreads();
    }
}

extern "C" void kernel_launch(void* const* d_in, const int* in_sizes, int n_in,
                              void* d_out, int out_size)
{
    const float* x   = (const float*)d_in[0];   // 4194304 f32
    const float* emb = (const float*)d_in[1];   // 32768 f32
    float* out_q = (float*)d_out;
    float* out_i = (float*)d_out + (size_t)4194304;

    cudaFuncSetAttribute(vq_hmma_kernel,
                         cudaFuncAttributeMaxDynamicSharedMemorySize, SM_TOTAL);
    vq_hmma_kernel<<<GRID, THREADS, SM_TOTAL>>>(x, emb, out_q, out_i);
}